// round 6
// baseline (speedup 1.0000x reference)
#include <cuda_runtime.h>
#include <cuda_bf16.h>
#include <math.h>

// ---------------------------------------------------------------------------
// MnistAdditionModule: LeNet (16384 digit images) -> per-digit log-softmax
//                      -> circuit over n1+n2 sums  => out [4096, 199] fp32
// ---------------------------------------------------------------------------

#define N_IMAGES 16384
#define BATCH    4096

typedef unsigned long long u64;

// packed-f32x2 helpers (sm_100+ double-rate fp32 path; PTX-only)
__device__ __forceinline__ u64 pack_dup(float v) {
    u64 r; asm("mov.b64 %0, {%1, %1};" : "=l"(r) : "f"(v)); return r;
}
__device__ __forceinline__ void fma2(u64& c, u64 a, u64 b) {
    asm("fma.rn.f32x2 %0, %1, %2, %0;" : "+l"(c) : "l"(a), "l"(b));
}
__device__ __forceinline__ float2 unpk(u64 v) {
    float2 f; asm("mov.b64 {%0, %1}, %2;" : "=f"(f.x), "=f"(f.y) : "l"(v)); return f;
}

// intermediate buffers (static device memory; no allocations allowed)
__device__ float g_out1[N_IMAGES * 6 * 12 * 12];   // conv1+pool+relu
__device__ float g_out2[N_IMAGES * 256];           // conv2+pool+relu (flattened)
__device__ float g_lp  [N_IMAGES * 10];            // per-image log-probs

// ---------------------------------------------------------------------------
// K1: conv1 (1->6, 5x5) + bias + maxpool2 + relu.  One block per image.
// Channel pairs packed into f32x2 accumulators; weights interleaved pair-major.
// ---------------------------------------------------------------------------
__global__ void conv1_kernel(const float* __restrict__ images,
                             const float* __restrict__ w,
                             const float* __restrict__ b) {
    __shared__ float img[784];
    __shared__ __align__(8) float ws2[300];   // 3 pairs x 25 x 2 (interleaved)
    __shared__ float bs[6];
    int n = blockIdx.x;
    const float* im = images + n * 784;
    for (int i = threadIdx.x; i < 784; i += blockDim.x) img[i] = im[i];
    if (threadIdx.x < 150) {
        int ch = threadIdx.x / 25, ij = threadIdx.x % 25;
        ws2[((ch >> 1) * 25 + ij) * 2 + (ch & 1)] = w[threadIdx.x];
    }
    if (threadIdx.x < 6) bs[threadIdx.x] = b[threadIdx.x];
    __syncthreads();

    int t = threadIdx.x;
    if (t >= 144) return;
    int oh = t / 12, ow = t - oh * 12;

    // 6x6 input window, duplicated into both f32x2 lanes
    u64 win2[6][6];
#pragma unroll
    for (int i = 0; i < 6; i++)
#pragma unroll
        for (int j = 0; j < 6; j++)
            win2[i][j] = pack_dup(img[(2 * oh + i) * 28 + (2 * ow + j)]);

    float* out = g_out1 + n * 864 + t;
#pragma unroll
    for (int p = 0; p < 3; p++) {               // channel pair
        u64 a00 = 0, a01 = 0, a10 = 0, a11 = 0;
        const u64* wp = (const u64*)&ws2[p * 50];
#pragma unroll
        for (int i = 0; i < 5; i++)
#pragma unroll
            for (int j = 0; j < 5; j++) {
                u64 wv = wp[i * 5 + j];         // (w_ch_even, w_ch_odd)
                fma2(a00, win2[i][j],         wv);
                fma2(a01, win2[i][j + 1],     wv);
                fma2(a10, win2[i + 1][j],     wv);
                fma2(a11, win2[i + 1][j + 1], wv);
            }
        float2 f00 = unpk(a00), f01 = unpk(a01), f10 = unpk(a10), f11 = unpk(a11);
        float me = fmaxf(fmaxf(f00.x, f01.x), fmaxf(f10.x, f11.x)) + bs[2 * p];
        float mo = fmaxf(fmaxf(f00.y, f01.y), fmaxf(f10.y, f11.y)) + bs[2 * p + 1];
        out[(2 * p)     * 144] = fmaxf(me, 0.f);
        out[(2 * p + 1) * 144] = fmaxf(mo, 0.f);
    }
}

// ---------------------------------------------------------------------------
// K2: conv2 (6->16, 5x5 on 12x12) + bias + maxpool2 + relu.
// 128 threads = 2 images x (16 pooled positions x 2 channel-quads).
// Each thread: 4 channels (= 2 f32x2-packed pairs) at one pooled position.
// ---------------------------------------------------------------------------
__global__ void conv2_kernel(const float* __restrict__ w,
                             const float* __restrict__ b) {
    __shared__ float in[1728];                 // 2 x 6 x 12 x 12
    __shared__ __align__(8) float ws2[2400];   // 8 pairs x 6 ic x 25 x 2
    __shared__ float bs[16];
    int n0 = blockIdx.x * 2;
    for (int i = threadIdx.x; i < 1728; i += 128) in[i] = g_out1[n0 * 864 + i];
    for (int i = threadIdx.x; i < 2400; i += 128) {
        int ch = i / 150, r = i - ch * 150;
        int ic = r / 25, ij = r - ic * 25;
        ws2[(((ch >> 1) * 6 + ic) * 25 + ij) * 2 + (ch & 1)] = w[i];
    }
    if (threadIdx.x < 16) bs[threadIdx.x] = b[threadIdx.x];
    __syncthreads();

    int t = threadIdx.x;
    int img = t >> 6, local = t & 63;
    int pos = local & 15, cg = local >> 4;     // cg: channel-quad 0..3
    int oh = pos >> 2, ow = pos & 3;
    const float* inp = in + img * 864;

    u64 acc[2][4] = {};                        // [pair-in-quad][a00,a01,a10,a11]
    for (int ic = 0; ic < 6; ic++) {
        u64 win2[6][6];
#pragma unroll
        for (int i = 0; i < 6; i++)
#pragma unroll
            for (int j = 0; j < 6; j++)
                win2[i][j] = pack_dup(inp[ic * 144 + (2 * oh + i) * 12 + (2 * ow + j)]);
#pragma unroll
        for (int q = 0; q < 2; q++) {
            int p = cg * 2 + q;
            const u64* wp = (const u64*)&ws2[((p * 6 + ic) * 25) * 2];
#pragma unroll
            for (int i = 0; i < 5; i++)
#pragma unroll
                for (int j = 0; j < 5; j++) {
                    u64 wv = wp[i * 5 + j];
                    fma2(acc[q][0], win2[i][j],         wv);
                    fma2(acc[q][1], win2[i][j + 1],     wv);
                    fma2(acc[q][2], win2[i + 1][j],     wv);
                    fma2(acc[q][3], win2[i + 1][j + 1], wv);
                }
        }
    }
    float* out = g_out2 + (n0 + img) * 256;
#pragma unroll
    for (int q = 0; q < 2; q++) {
        float2 f0 = unpk(acc[q][0]), f1 = unpk(acc[q][1]);
        float2 f2 = unpk(acc[q][2]), f3 = unpk(acc[q][3]);
        int che = cg * 4 + 2 * q;
        float me = fmaxf(fmaxf(f0.x, f1.x), fmaxf(f2.x, f3.x)) + bs[che];
        float mo = fmaxf(fmaxf(f0.y, f1.y), fmaxf(f2.y, f3.y)) + bs[che + 1];
        out[che * 16 + pos]       = fmaxf(me, 0.f);
        out[(che + 1) * 16 + pos] = fmaxf(mo, 0.f);
    }
}

// ---------------------------------------------------------------------------
// K3: fc1(256->120)+relu, fc2(120->84)+relu, fc3(84->10), log_softmax.
// 32 images/block, 256 threads. f32x2 image-pair packing: activations stored
// TRANSPOSED [k][img] with stride 34 (even -> aligned LDS.64 of image pairs,
// warp-uniform address -> broadcast). Weights k-major, padded strides 121/85
// (conflict-free transposed stores and lane-consecutive loads). Per k-step:
// 2 LDS.64 + 4 LDS.32 + 8 FFMA2 = 16 MACs -> FMA-pipe cycles halved.
// ---------------------------------------------------------------------------
#define FC_SMEM_FLOATS (30976 + 10200 + 840 + 120 + 84 + 16 + 8704 + 4080 + 320)
#define FC_SMEM_BYTES  (FC_SMEM_FLOATS * 4)

__global__ void fc_kernel(const float* __restrict__ w1, const float* __restrict__ b1,
                          const float* __restrict__ w2, const float* __restrict__ b2,
                          const float* __restrict__ w3, const float* __restrict__ b3) {
    extern __shared__ float sm[];
    float* s_w1 = sm;              // [256][121] k-major, padded
    float* s_w2 = s_w1 + 30976;    // [120][85]  k-major, padded
    float* s_w3 = s_w2 + 10200;    // [84][10]   k-major
    float* s_b1 = s_w3 + 840;      // 120
    float* s_b2 = s_b1 + 120;      // 84
    float* s_b3 = s_b2 + 84;       // 16
    float* s_xT = s_b3 + 16;       // [256][34] transposed acts (8704)
    float* s_h1T = s_xT + 8704;    // [120][34] (4080)
    float* s_h2T = s_xT;           // [84][34]  aliases dead x region
    float* s_z  = s_h1T + 4080;    // [32][10]

    int t = threadIdx.x;           // 256 threads
    for (int i = t; i < 30720; i += 256) {
        int j = i >> 8, k = i & 255;                 // w1 is [120][256]
        s_w1[k * 121 + j] = w1[i];
    }
    for (int i = t; i < 10080; i += 256) {
        int j = i / 120, k = i - j * 120;
        s_w2[k * 85 + j] = w2[i];
    }
    for (int i = t; i < 840; i += 256) {
        int j = i / 84, k = i - j * 84;
        s_w3[k * 10 + j] = w3[i];
    }
    if (t < 120) s_b1[t] = b1[t];
    if (t < 84)  s_b2[t] = b2[t];
    if (t < 16)  s_b3[t] = (t < 10) ? b3[t] : 0.f;

    int n0 = blockIdx.x * 32;
    for (int i = t; i < 8192; i += 256) {
        int img = i >> 8, k = i & 255;
        s_xT[k * 34 + img] = g_out2[n0 * 256 + i];
    }
    __syncthreads();

    int gg = t >> 5, jj = t & 31;   // warp gg handles images [4gg, 4gg+4)

    // fc1: 4 images (2 f32x2 pairs) x 4 outputs per thread; jj < 30
    if (jj < 30) {
        u64 acc[2][4];
#pragma unroll
        for (int u = 0; u < 4; u++) {
            u64 bv = pack_dup(s_b1[jj + 30 * u]);
            acc[0][u] = bv; acc[1][u] = bv;
        }
        const float* xb = s_xT + 4 * gg;
#pragma unroll 4
        for (int k = 0; k < 256; k++) {
            u64 x01 = *(const u64*)(xb + k * 34);
            u64 x23 = *(const u64*)(xb + k * 34 + 2);
            const float* wr = s_w1 + k * 121 + jj;
            u64 wa = pack_dup(wr[0]),  wb = pack_dup(wr[30]);
            u64 wc = pack_dup(wr[60]), wd = pack_dup(wr[90]);
            fma2(acc[0][0], x01, wa); fma2(acc[1][0], x23, wa);
            fma2(acc[0][1], x01, wb); fma2(acc[1][1], x23, wb);
            fma2(acc[0][2], x01, wc); fma2(acc[1][2], x23, wc);
            fma2(acc[0][3], x01, wd); fma2(acc[1][3], x23, wd);
        }
#pragma unroll
        for (int u = 0; u < 4; u++) {
            float2 e = unpk(acc[0][u]), f = unpk(acc[1][u]);
            float* hp = s_h1T + (jj + 30 * u) * 34 + 4 * gg;
            hp[0] = fmaxf(e.x, 0.f); hp[1] = fmaxf(e.y, 0.f);
            hp[2] = fmaxf(f.x, 0.f); hp[3] = fmaxf(f.y, 0.f);
        }
    }
    __syncthreads();

    // fc2: same scheme; jj < 21, outputs j = jj + 21u. Writes alias x region.
    if (jj < 21) {
        u64 acc[2][4];
#pragma unroll
        for (int u = 0; u < 4; u++) {
            u64 bv = pack_dup(s_b2[jj + 21 * u]);
            acc[0][u] = bv; acc[1][u] = bv;
        }
        const float* xb = s_h1T + 4 * gg;
#pragma unroll 4
        for (int k = 0; k < 120; k++) {
            u64 x01 = *(const u64*)(xb + k * 34);
            u64 x23 = *(const u64*)(xb + k * 34 + 2);
            const float* wr = s_w2 + k * 85 + jj;
            u64 wa = pack_dup(wr[0]),  wb = pack_dup(wr[21]);
            u64 wc = pack_dup(wr[42]), wd = pack_dup(wr[63]);
            fma2(acc[0][0], x01, wa); fma2(acc[1][0], x23, wa);
            fma2(acc[0][1], x01, wb); fma2(acc[1][1], x23, wb);
            fma2(acc[0][2], x01, wc); fma2(acc[1][2], x23, wc);
            fma2(acc[0][3], x01, wd); fma2(acc[1][3], x23, wd);
        }
#pragma unroll
        for (int u = 0; u < 4; u++) {
            float2 e = unpk(acc[0][u]), f = unpk(acc[1][u]);
            float* hp = s_h2T + (jj + 21 * u) * 34 + 4 * gg;
            hp[0] = fmaxf(e.x, 0.f); hp[1] = fmaxf(e.y, 0.f);
            hp[2] = fmaxf(f.x, 0.f); hp[3] = fmaxf(f.y, 0.f);
        }
    }
    __syncthreads();

    // fc3: 32 img x 10 outputs = 320 dots over 84 (tiny, strided reads)
    for (int o = t; o < 320; o += 256) {
        int g = o / 10, j = o - g * 10;
        const float* xp = s_h2T + g;
        float acc = s_b3[j];
#pragma unroll
        for (int k = 0; k < 84; k++) acc = fmaf(xp[k * 34], s_w3[k * 10 + j], acc);
        s_z[g * 10 + j] = acc;
    }
    __syncthreads();

    // log_softmax per image
    if (t < 32) {
        const float* z = s_z + t * 10;
        float m = -1e30f;
#pragma unroll
        for (int i = 0; i < 10; i++) m = fmaxf(m, z[i]);
        float s = 0.f;
#pragma unroll
        for (int i = 0; i < 10; i++) s += __expf(z[i] - m);
        float lse = __logf(s) + m;
        float* out = g_lp + (n0 + t) * 10;
#pragma unroll
        for (int i = 0; i < 10; i++) out[i] = z[i] - lse;
    }
}

// ---------------------------------------------------------------------------
// K4: circuit. out[s] = log( sum_i p1[i]*p2[s-i] ) + m1 + m2  (exact
// linear-space equivalent of the grouped logsumexp). p2 is zero-padded so the
// inner loop is a UNIFORM 100 iterations (no intra-warp divergence):
// out[t] = log( sum_{i=0}^{99} p1[i] * p2p[t+99-i] ).
// ---------------------------------------------------------------------------
__global__ void circuit_kernel(float* __restrict__ out) {
    __shared__ float p1[100];
    __shared__ float p2p[304];     // p2p[x] = p2[x-99] for 99<=x<=198, else 0
    __shared__ float msum[2];
    int b = blockIdx.x;
    const float* lp = g_lp + b * 40;
    int t = threadIdx.x;   // 256 threads

    if (t == 0) {
        float m0 = -1e30f, m1 = -1e30f, m2 = -1e30f, m3 = -1e30f;
#pragma unroll
        for (int i = 0; i < 10; i++) {
            m0 = fmaxf(m0, lp[i]);
            m1 = fmaxf(m1, lp[10 + i]);
            m2 = fmaxf(m2, lp[20 + i]);
            m3 = fmaxf(m3, lp[30 + i]);
        }
        msum[0] = m0 + m1;
        msum[1] = m2 + m3;
    }
    __syncthreads();
    if (t < 100) p1[t] = __expf(lp[t / 10] + lp[10 + t % 10] - msum[0]);
    for (int x = t; x < 304; x += 256) {
        float v = 0.f;
        if (x >= 99 && x <= 198) {
            int k = x - 99;
            v = __expf(lp[20 + k / 10] + lp[30 + k % 10] - msum[1]);
        }
        p2p[x] = v;
    }
    __syncthreads();
    if (t < 199) {
        const float* q = p2p + t;          // q[99-i] = p2p[t+99-i]
        float s = 0.f;
#pragma unroll 4
        for (int i = 0; i < 100; i++) s = fmaf(p1[i], q[99 - i], s);
        out[b * 199 + t] = __logf(s) + msum[0] + msum[1];
    }
}

// ---------------------------------------------------------------------------
extern "C" void kernel_launch(void* const* d_in, const int* in_sizes, int n_in,
                              void* d_out, int out_size) {
    const float* images = (const float*)d_in[0];
    const float* c1w    = (const float*)d_in[1];
    const float* c1b    = (const float*)d_in[2];
    const float* c2w    = (const float*)d_in[3];
    const float* c2b    = (const float*)d_in[4];
    const float* f1w    = (const float*)d_in[5];
    const float* f1b    = (const float*)d_in[6];
    const float* f2w    = (const float*)d_in[7];
    const float* f2b    = (const float*)d_in[8];
    const float* f3w    = (const float*)d_in[9];
    const float* f3b    = (const float*)d_in[10];
    float* out = (float*)d_out;

    cudaFuncSetAttribute(fc_kernel, cudaFuncAttributeMaxDynamicSharedMemorySize,
                         FC_SMEM_BYTES);

    conv1_kernel<<<N_IMAGES, 160>>>(images, c1w, c1b);
    conv2_kernel<<<N_IMAGES / 2, 128>>>(c2w, c2b);
    fc_kernel<<<N_IMAGES / 32, 256, FC_SMEM_BYTES>>>(f1w, f1b, f2w, f2b, f3w, f3b);
    circuit_kernel<<<BATCH, 256>>>(out);
}